// round 10
// baseline (speedup 1.0000x reference)
#include <cuda_runtime.h>
#include <cuda_fp16.h>
#include <math.h>
#include <stdint.h>

#define NN 60000
#define EE 300000
#define AA 8000
#define GG 256
#define DD 128
#define HH 8
#define CC 16
#define LL 3
#define RBFD 16
#define SBFD 112

// ---------------- scratch (static device globals; no allocation) ----------------
__device__ float g_featA[NN * DD];
__device__ float g_featB[NN * DD];
__device__ float g_featC[NN * DD];
__device__ float g_featD[NN * DD];
__device__ float g_featE[NN * DD];
__device__ float g_featF[NN * DD];
__device__ float g_sw[(size_t)EE * DD];   // CSR-ordered per-edge sbf weights
__device__ float g_at2[AA * DD];
__device__ float g_results[AA];
__device__ float g_gsum[GG];
__device__ float g_gvar[GG];
__device__ float g_gcnt[GG];
// CSR scratch (indices constant per call; built once, reused)
__device__ int g_eoff[NN + 1];
__device__ int g_epos[NN];
__device__ int g_ecsr[EE];
__device__ int g_pinv[EE];
__device__ int g_esrcc[EE];
__device__ int g_paic[EE];
__device__ int g_aoff[AA + 1];
__device__ int g_apos[AA];
__device__ int g_acsr[NN];

// ---------------- helpers ----------------
__device__ __forceinline__ float silu_f(float v) { return v / (1.f + expf(-v)); }

__device__ __forceinline__ uint32_t pack_h2(float x, float y) {
    __half2 h = __floats2half2_rn(x, y);
    return *(uint32_t*)&h;
}
__device__ __forceinline__ float h2_lo(uint32_t u) {
    __half2 h = *(__half2*)&u;
    return __low2float(h);
}
__device__ __forceinline__ float h2_hi(uint32_t u) {
    __half2 h = *(__half2*)&u;
    return __high2float(h);
}

__device__ __forceinline__ void mma_f16(float* acc, const uint32_t* a, const uint32_t* b) {
    asm volatile(
        "mma.sync.aligned.m16n8k16.row.col.f32.f16.f16.f32 "
        "{%0,%1,%2,%3}, {%4,%5,%6,%7}, {%8,%9}, {%0,%1,%2,%3};\n"
        : "+f"(acc[0]), "+f"(acc[1]), "+f"(acc[2]), "+f"(acc[3])
        : "r"(a[0]), "r"(a[1]), "r"(a[2]), "r"(a[3]), "r"(b[0]), "r"(b[1]));
}

__device__ __forceinline__ uint32_t sptr(const void* p) {
    return (uint32_t)__cvta_generic_to_shared(p);
}
#define LDSM4(r0, r1, r2, r3, addr)                                              \
    asm volatile("ldmatrix.sync.aligned.m8n8.x4.shared.b16 {%0,%1,%2,%3}, [%4];" \
                 : "=r"(r0), "=r"(r1), "=r"(r2), "=r"(r3) : "r"(addr))

#define EP_SILU 1
#define EP_RES 2
#define EP_MUL 4
#define EP_GNA 8
#define EP_GNRES 16

// ---------------- multi-descriptor fp16 3-term tensor-core GEMM, N = 128 ------
// C[M,128] = ep(A[M,K] @ W[K,128] + bias); product = ah*wh + ah*wl + al*wh.
// Up to 5 independent GEMMs per launch via blockIdx.y. Optional graph-norm on
// A rows (EP_GNA) or on res rows (EP_GNRES). Optional output-row perm.
struct GDesc {
    const float *A, *W, *bias, *res, *mul;
    float* C;
    const int* perm;
    int M, K, flags;
};
struct GBatch { GDesc d[5]; };

#define SAW 12

__global__ __launch_bounds__(256, 2) void gemm_h3(
    GBatch gb, const int* __restrict__ gnb, const float* __restrict__ gsum,
    const float* __restrict__ gvar, const float* __restrict__ gcnt)
{
    __shared__ uint32_t AsH[2][128][SAW];
    __shared__ uint32_t AsL[2][128][SAW];
    __shared__ uint32_t WsH[2][128][SAW];
    __shared__ uint32_t WsL[2][128][SAW];

    const GDesc d = gb.d[blockIdx.y];
    const int row0 = blockIdx.x * 128;
    if (row0 >= d.M) return;

    const int tid = threadIdx.x;
    const int wid = tid >> 5, lane = tid & 31;
    const int g = lane >> 2, tig = lane & 3;
    const int m0 = (wid & 1) * 64, n0 = (wid >> 1) * 32;

    const int arow = tid >> 1, akf = (tid & 1) * 8, akw = (tid & 1) * 4;
    const int wn = tid & 127, wkb = (tid >> 7) * 8, wkw = (tid >> 7) * 4;
    const int a_r = lane & 15, a_kw = (lane >> 4) * 4;
    const int b_nadd = ((lane >> 4) << 3) | (lane & 7), b_kw = ((lane >> 3) & 1) * 4;

    float acc[4][4][4];
#pragma unroll
    for (int mi = 0; mi < 4; mi++)
#pragma unroll
        for (int ni = 0; ni < 4; ni++)
#pragma unroll
            for (int r = 0; r < 4; r++) acc[mi][ni][r] = 0.f;

    const int nc = d.K >> 4;
    const bool arow_ok = (row0 + arow) < d.M;
    const float* aptr = d.A + (size_t)(row0 + arow) * d.K + akf;

    float amean = 0.f, ars = 1.f;
    const bool gna = (d.flags & EP_GNA) != 0;
    if (gna && arow_ok) {
        int gg = gnb[row0 + arow];
        float inv = 1.f / (gcnt[gg] * 128.f);
        amean = gsum[gg] * inv;
        ars = rsqrtf(gvar[gg] * inv + 1e-8f);
    }

    float fa[8], fw[8];
    auto fetch = [&](int c) {
        const float* ap = aptr + (size_t)c * 16;
        if (arow_ok) {
            *(float4*)&fa[0] = *(const float4*)ap;
            *(float4*)&fa[4] = *(const float4*)(ap + 4);
        } else {
#pragma unroll
            for (int p = 0; p < 8; p++) fa[p] = 0.f;
        }
        if (gna) {
#pragma unroll
            for (int p = 0; p < 8; p++) fa[p] = (fa[p] - amean) * ars;
        }
        const float* wp = d.W + (size_t)c * 16 * 128;
#pragma unroll
        for (int j = 0; j < 8; j++) fw[j] = wp[(size_t)(wkb + j) * 128 + wn];
    };
    auto stage = [&](int b) {
        uint32_t h[4], l[4];
#pragma unroll
        for (int p = 0; p < 4; p++) {
            h[p] = pack_h2(fa[2 * p], fa[2 * p + 1]);
            l[p] = pack_h2(fa[2 * p] - h2_lo(h[p]), fa[2 * p + 1] - h2_hi(h[p]));
        }
        *(uint4*)&AsH[b][arow][akw] = make_uint4(h[0], h[1], h[2], h[3]);
        *(uint4*)&AsL[b][arow][akw] = make_uint4(l[0], l[1], l[2], l[3]);
#pragma unroll
        for (int p = 0; p < 4; p++) {
            h[p] = pack_h2(fw[2 * p], fw[2 * p + 1]);
            l[p] = pack_h2(fw[2 * p] - h2_lo(h[p]), fw[2 * p + 1] - h2_hi(h[p]));
        }
        *(uint4*)&WsH[b][wn][wkw] = make_uint4(h[0], h[1], h[2], h[3]);
        *(uint4*)&WsL[b][wn][wkw] = make_uint4(l[0], l[1], l[2], l[3]);
    };

    fetch(0);
    stage(0);
    __syncthreads();

    int cur = 0;
    for (int c = 0; c < nc; c++) {
        const bool pf = (c + 1 < nc);
        if (pf) fetch(c + 1);
        uint32_t bH[4][2], bL[4][2];
#pragma unroll
        for (int hh = 0; hh < 2; hh++) {
            int n = n0 + hh * 16 + b_nadd;
            LDSM4(bH[2 * hh][0], bH[2 * hh][1], bH[2 * hh + 1][0], bH[2 * hh + 1][1],
                  sptr(&WsH[cur][n][b_kw]));
            LDSM4(bL[2 * hh][0], bL[2 * hh][1], bL[2 * hh + 1][0], bL[2 * hh + 1][1],
                  sptr(&WsL[cur][n][b_kw]));
        }
#pragma unroll
        for (int mi = 0; mi < 4; mi++) {
            int r = m0 + mi * 16 + a_r;
            uint32_t aH[4], aL[4];
            LDSM4(aH[0], aH[1], aH[2], aH[3], sptr(&AsH[cur][r][a_kw]));
            LDSM4(aL[0], aL[1], aL[2], aL[3], sptr(&AsL[cur][r][a_kw]));
#pragma unroll
            for (int ni = 0; ni < 4; ni++) {
                mma_f16(acc[mi][ni], aH, bH[ni]);
                mma_f16(acc[mi][ni], aH, bL[ni]);
                mma_f16(acc[mi][ni], aL, bH[ni]);
            }
        }
        if (pf) stage(cur ^ 1);
        __syncthreads();
        cur ^= 1;
    }

    // ---- epilogue ----
#pragma unroll
    for (int mi = 0; mi < 4; mi++) {
        int rbase = row0 + m0 + mi * 16 + g;
#pragma unroll
        for (int ni = 0; ni < 4; ni++) {
            int cidx = n0 + ni * 8 + tig * 2;
#pragma unroll
            for (int half = 0; half < 2; half++) {
                int r = rbase + half * 8;
                if (r >= d.M) continue;
                float vx = acc[mi][ni][half * 2 + 0];
                float vy = acc[mi][ni][half * 2 + 1];
                if (d.bias) { vx += d.bias[cidx]; vy += d.bias[cidx + 1]; }
                if (d.flags & EP_SILU) { vx = silu_f(vx); vy = silu_f(vy); }
                size_t off = (size_t)r * 128 + cidx;
                if (d.flags & EP_RES) {
                    float2 rr = *(const float2*)(d.res + off);
                    if (d.flags & EP_GNRES) {
                        int gg = gnb[r];
                        float inv = 1.f / (gcnt[gg] * 128.f);
                        float mean = gsum[gg] * inv;
                        float rs = rsqrtf(gvar[gg] * inv + 1e-8f);
                        rr.x = (rr.x - mean) * rs;
                        rr.y = (rr.y - mean) * rs;
                    }
                    vx += rr.x; vy += rr.y;
                }
                if (d.flags & EP_MUL) {
                    float2 mm = *(const float2*)(d.mul + off);
                    vx *= mm.x; vy *= mm.y;
                }
                size_t orow = d.perm ? (size_t)d.perm[r] : (size_t)r;
                *(float2*)(d.C + orow * 128 + cidx) = make_float2(vx, vy);
            }
        }
    }
}

// ---------------- chained AA GEMM kernel: gather prologue + up to 3 stages ----
// Tiles resident in smem (fp16 hi/lo, row stride 68 words — conflict-free LDSM,
// validated in R6). Optional final per-row dot (readout w3) accumulated into
// dotres (each row owned by exactly one block: no atomics).
#define CF_SILU 1

struct CStage { const float* W; const float* bias; float* out; int flags; int src; int dst; };
struct CArgs {
    CStage st[3]; int ns;
    const float* gsrc;
    const float* dotw; const float* dotb; float* dotres;
};
struct CArgs2 { CArgs a[2]; };

#define CHAIN_SMEM 163840

__global__ __launch_bounds__(256, 1) void chain_gemm(
    CArgs2 ca2, int M, const int* __restrict__ goff, const int* __restrict__ gcsr)
{
    const CArgs ca = ca2.a[blockIdx.y];
    extern __shared__ uint32_t smw[];
    uint32_t* XH = smw;             // 128*68
    uint32_t* XL = smw + 8704;
    uint32_t* TH = smw + 17408;
    uint32_t* TL = smw + 26112;
    uint32_t* WHs = smw + 34816;    // [2][1536]
    uint32_t* WLs = smw + 37888;

    const int tid = threadIdx.x, wid = tid >> 5, lane = tid & 31;
    const int g = lane >> 2, tig = lane & 3;
    const int m0 = (wid & 1) * 64, n0 = (wid >> 1) * 32;
    const int row0 = blockIdx.x * 128;
    const int wn = tid & 127, wkb = (tid >> 7) * 8, wkw = (tid >> 7) * 4;
    const int a_r = lane & 15, a_kw = (lane >> 4) * 4;
    const int b_nadd = ((lane >> 4) << 3) | (lane & 7), b_kw = ((lane >> 3) & 1) * 4;

    // ---- gather prologue: warp per row, CSR sum of gsrc rows -> X ----
    for (int rr = wid; rr < 128; rr += 8) {
        int a = row0 + rr;
        float4 acc = make_float4(0, 0, 0, 0);
        if (a < M) {
            int s = goff[a], e = goff[a + 1];
            for (int j = s; j < e; j++) {
                int n = gcsr[j];
                float4 v = ((const float4*)(ca.gsrc + (size_t)n * 128))[lane];
                acc.x += v.x; acc.y += v.y; acc.z += v.z; acc.w += v.w;
            }
        }
        uint32_t h0 = pack_h2(acc.x, acc.y), h1 = pack_h2(acc.z, acc.w);
        XH[rr * 68 + lane * 2] = h0;
        XH[rr * 68 + lane * 2 + 1] = h1;
        XL[rr * 68 + lane * 2]     = pack_h2(acc.x - h2_lo(h0), acc.y - h2_hi(h0));
        XL[rr * 68 + lane * 2 + 1] = pack_h2(acc.z - h2_lo(h1), acc.w - h2_hi(h1));
    }
    __syncthreads();

    for (int s = 0; s < ca.ns; s++) {
        const CStage st = ca.st[s];
        const uint32_t* SH = st.src ? TH : XH;
        const uint32_t* SL = st.src ? TL : XL;
        uint32_t* DH = (st.dst == 1) ? TH : XH;
        uint32_t* DL = (st.dst == 1) ? TL : XL;

        float acc[4][4][4];
#pragma unroll
        for (int mi = 0; mi < 4; mi++)
#pragma unroll
            for (int ni = 0; ni < 4; ni++)
#pragma unroll
                for (int r = 0; r < 4; r++) acc[mi][ni][r] = 0.f;

        float fw[8];
        auto wfetch = [&](int c) {
            const float* wp = st.W + (size_t)c * 16 * 128;
#pragma unroll
            for (int j = 0; j < 8; j++) fw[j] = wp[(size_t)(wkb + j) * 128 + wn];
        };
        auto wstage = [&](int b) {
            uint32_t* WH = WHs + b * 1536;
            uint32_t* WL = WLs + b * 1536;
#pragma unroll
            for (int p = 0; p < 4; p++) {
                uint32_t h = pack_h2(fw[2 * p], fw[2 * p + 1]);
                WH[wn * 12 + wkw + p] = h;
                WL[wn * 12 + wkw + p] =
                    pack_h2(fw[2 * p] - h2_lo(h), fw[2 * p + 1] - h2_hi(h));
            }
        };
        wfetch(0); wstage(0);
        __syncthreads();
        int cur = 0;
        for (int c = 0; c < 8; c++) {
            if (c < 7) wfetch(c + 1);
            const uint32_t* WH = WHs + cur * 1536;
            const uint32_t* WL = WLs + cur * 1536;
            uint32_t bH[4][2], bL[4][2];
#pragma unroll
            for (int hh = 0; hh < 2; hh++) {
                int n = n0 + hh * 16 + b_nadd;
                LDSM4(bH[2 * hh][0], bH[2 * hh][1], bH[2 * hh + 1][0], bH[2 * hh + 1][1],
                      sptr(&WH[n * 12 + b_kw]));
                LDSM4(bL[2 * hh][0], bL[2 * hh][1], bL[2 * hh + 1][0], bL[2 * hh + 1][1],
                      sptr(&WL[n * 12 + b_kw]));
            }
#pragma unroll
            for (int mi = 0; mi < 4; mi++) {
                int r = m0 + mi * 16 + a_r;
                uint32_t aH[4], aL[4];
                LDSM4(aH[0], aH[1], aH[2], aH[3], sptr(&SH[r * 68 + c * 8 + a_kw]));
                LDSM4(aL[0], aL[1], aL[2], aL[3], sptr(&SL[r * 68 + c * 8 + a_kw]));
#pragma unroll
                for (int ni = 0; ni < 4; ni++) {
                    mma_f16(acc[mi][ni], aH, bH[ni]);
                    mma_f16(acc[mi][ni], aH, bL[ni]);
                    mma_f16(acc[mi][ni], aL, bH[ni]);
                }
            }
            if (c < 7) wstage(cur ^ 1);
            __syncthreads();
            cur ^= 1;
        }

        const int f = st.flags;
#pragma unroll
        for (int mi = 0; mi < 4; mi++) {
#pragma unroll
            for (int ni = 0; ni < 4; ni++) {
                int cidx = n0 + ni * 8 + tig * 2;
                int w = cidx >> 1;
#pragma unroll
                for (int half = 0; half < 2; half++) {
                    int rl = m0 + mi * 16 + g + half * 8;
                    int r = row0 + rl;
                    float vx = acc[mi][ni][half * 2 + 0];
                    float vy = acc[mi][ni][half * 2 + 1];
                    if (st.bias) { vx += st.bias[cidx]; vy += st.bias[cidx + 1]; }
                    if (f & CF_SILU) { vx = silu_f(vx); vy = silu_f(vy); }
                    if (st.out && r < M)
                        *(float2*)(st.out + (size_t)r * 128 + cidx) = make_float2(vx, vy);
                    if (st.dst != 2) {
                        uint32_t h = pack_h2(vx, vy);
                        DH[rl * 68 + w] = h;
                        DL[rl * 68 + w] = pack_h2(vx - h2_lo(h), vy - h2_hi(h));
                    }
                }
            }
        }
        __syncthreads();
    }

    // ---- optional per-row dot (readout w3) ----
    if (ca.dotw) {
        for (int rr = wid; rr < 128; rr += 8) {
            int a = row0 + rr;
            float s = 0.f;
#pragma unroll
            for (int t = 0; t < 4; t++) {
                int c = lane + t * 32;
                int w = c >> 1;
                uint32_t hw = XH[rr * 68 + w], lw = XL[rr * 68 + w];
                float val = (c & 1) ? (h2_hi(hw) + h2_hi(lw)) : (h2_lo(hw) + h2_lo(lw));
                s += val * ca.dotw[c];
            }
#pragma unroll
            for (int o = 16; o; o >>= 1) s += __shfl_xor_sync(0xffffffffu, s, o);
            if (!lane && a < M) ca.dotres[a] += s + ca.dotb[0];
        }
    }
}

// ---------------- CSR construction ----------------
__global__ void hist_seg(const int* __restrict__ idx, int n, int* __restrict__ deg) {
    int t = blockIdx.x * blockDim.x + threadIdx.x;
    if (t >= n) return;
    atomicAdd(&deg[idx[t] + 1], 1);
}

__global__ void scan_offsets(int* __restrict__ deg, int n) {
    __shared__ int buf[1024];
    __shared__ int carry;
    if (threadIdx.x == 0) carry = 0;
    __syncthreads();
    for (int base = 0; base < n; base += 1024) {
        int i = base + threadIdx.x;
        int v = (i < n) ? deg[i + 1] : 0;
        buf[threadIdx.x] = v;
        __syncthreads();
        for (int off = 1; off < 1024; off <<= 1) {
            int t = (threadIdx.x >= off) ? buf[threadIdx.x - off] : 0;
            __syncthreads();
            buf[threadIdx.x] += t;
            __syncthreads();
        }
        int total = buf[1023];
        if (i < n) deg[i + 1] = buf[threadIdx.x] + carry;
        __syncthreads();
        if (threadIdx.x == 0) carry += total;
        __syncthreads();
    }
}

__global__ void fill_csr(const int* __restrict__ idx, int n, int* __restrict__ pos,
                         int* __restrict__ csr, int* __restrict__ pinv) {
    int t = blockIdx.x * blockDim.x + threadIdx.x;
    if (t >= n) return;
    int p = atomicAdd(&pos[idx[t]], 1);
    csr[p] = t;
    if (pinv) pinv[t] = p;
}

__global__ void perm_edges(const int* __restrict__ ecsr, const int* __restrict__ esrc,
                           const int* __restrict__ pai, int* __restrict__ esrc_c,
                           int* __restrict__ pai_c) {
    int j = blockIdx.x * blockDim.x + threadIdx.x;
    if (j >= EE) return;
    int e = ecsr[j];
    esrc_c[j] = esrc[e];
    pai_c[j] = pai[e];
}

// ---------------- fused CSR attention: single pass, no max shift --------------
__global__ void attn_csr(const float* __restrict__ q, const float* __restrict__ k,
                         const float* __restrict__ v, const float* __restrict__ ek,
                         const float* __restrict__ swc, const int* __restrict__ esrc_c,
                         const int* __restrict__ pai_c, const int* __restrict__ off,
                         float* __restrict__ out) {
    int idx = blockIdx.x * blockDim.x + threadIdx.x;
    int w = idx >> 5, lane = idx & 31;
    if (w >= NN) return;
    int s0 = off[w], s1 = off[w + 1];
    float4 q4 = ((const float4*)(q + (size_t)w * DD))[lane];

    float4 acc = make_float4(0, 0, 0, 0);
    float den = 0.f;
    for (int j = s0; j < s1; j++) {
        int sn = esrc_c[j], pa = pai_c[j];
        float4 k4 = ((const float4*)(k + (size_t)sn * DD))[lane];
        float4 e4 = ((const float4*)(ek + (size_t)pa * DD))[lane];
        float p = q4.x * (k4.x + e4.x) + q4.y * (k4.y + e4.y) +
                  q4.z * (k4.z + e4.z) + q4.w * (k4.w + e4.w);
        p += __shfl_xor_sync(0xffffffffu, p, 1);
        p += __shfl_xor_sync(0xffffffffu, p, 2);
        float ex = expf(p * 0.25f);
        den += ex;
        float4 v4 = ((const float4*)(v + (size_t)sn * DD))[lane];
        float4 s4 = ((const float4*)(swc + (size_t)j * DD))[lane];
        acc.x += ex * (v4.x + e4.x) * s4.x;
        acc.y += ex * (v4.y + e4.y) * s4.y;
        acc.z += ex * (v4.z + e4.z) * s4.z;
        acc.w += ex * (v4.w + e4.w) * s4.w;
    }
    float inv = 1.f / (den + 1e-16f);
    acc.x *= inv; acc.y *= inv; acc.z *= inv; acc.w *= inv;
    ((float4*)(out + (size_t)w * DD))[lane] = acc;
}

// ---------------- norm / misc kernels ----------------
__global__ void count_nodes(const int* __restrict__ batch, float* __restrict__ cnt) {
    int n = blockIdx.x * blockDim.x + threadIdx.x;
    if (n >= NN) return;
    atomicAdd(&cnt[batch[n]], 1.f);
}

__global__ void gn_sum(const float* __restrict__ hbuf, const int* __restrict__ batch,
                       float* __restrict__ gsum) {
    int idx = blockIdx.x * blockDim.x + threadIdx.x;
    int warp = idx >> 5, lane = idx & 31;
    if (warp >= NN) return;
    float4 v = ((const float4*)(hbuf + (size_t)warp * DD))[lane];
    float s = v.x + v.y + v.z + v.w;
#pragma unroll
    for (int o = 16; o; o >>= 1) s += __shfl_xor_sync(0xffffffffu, s, o);
    if (!lane) atomicAdd(&gsum[batch[warp]], s);
}

__global__ void gn_var(const float* __restrict__ hbuf, const int* __restrict__ batch,
                       const float* __restrict__ gsum, const float* __restrict__ gcnt,
                       float* __restrict__ gvar) {
    int idx = blockIdx.x * blockDim.x + threadIdx.x;
    int warp = idx >> 5, lane = idx & 31;
    if (warp >= NN) return;
    int g = batch[warp];
    float mean = gsum[g] / (gcnt[g] * DD);
    float4 v = ((const float4*)(hbuf + (size_t)warp * DD))[lane];
    float a = v.x - mean, b = v.y - mean, c = v.z - mean, d = v.w - mean;
    float s = a * a + b * b + c * c + d * d;
#pragma unroll
    for (int o = 16; o; o >>= 1) s += __shfl_xor_sync(0xffffffffu, s, o);
    if (!lane) atomicAdd(&gvar[g], s);
}

__global__ void final_scatter(const float* __restrict__ results, const int* __restrict__ abatch,
                              float* __restrict__ out) {
    int a = blockIdx.x * blockDim.x + threadIdx.x;
    if (a >= AA) return;
    atomicAdd(&out[abatch[a]], results[a] * (1.0f / (float)LL));
}

// ---------------- host orchestration ----------------
static GDesc mkd(const float* A, const float* W, const float* bias, const float* res,
                 const float* mul, float* C, const int* perm, int M, int K, int flags) {
    GDesc d; d.A = A; d.W = W; d.bias = bias; d.res = res; d.mul = mul;
    d.C = C; d.perm = perm; d.M = M; d.K = K; d.flags = flags; return d;
}

extern "C" void kernel_launch(void* const* d_in, const int* in_sizes, int n_in,
                              void* d_out, int out_size) {
    const float* x         = (const float*)d_in[0];
    const float* node_rbf  = (const float*)d_in[1];
    const float* edge_sbf  = (const float*)d_in[2];
    const int*   eidx      = (const int*)d_in[3];
    const int*   pai       = (const int*)d_in[4];
    const int*   idx0      = (const int*)d_in[5];
    const int*   abatch    = (const int*)d_in[6];
    const int*   nbatch    = (const int*)d_in[7];
    const float* edgenn_w1 = (const float*)d_in[8];
    const float* edgenn_b1 = (const float*)d_in[9];
    const float* edgenn_w2 = (const float*)d_in[10];
    const float* edgenn_b2 = (const float*)d_in[11];
    const float* conv_wq   = (const float*)d_in[12];
    const float* conv_wk   = (const float*)d_in[13];
    const float* conv_wv   = (const float*)d_in[14];
    const float* conv_we   = (const float*)d_in[15];
    const float* conv_wsbf = (const float*)d_in[16];
    const float* conv_bsbf = (const float*)d_in[17];
    const float* conv_wrbf = (const float*)d_in[18];
    const float* dense_w   = (const float*)d_in[19];
    const float* dense_b   = (const float*)d_in[20];
    const float* bf_w      = (const float*)d_in[21];
    const float* bf_b      = (const float*)d_in[22];
    const float* af_w      = (const float*)d_in[23];
    const float* af_b      = (const float*)d_in[24];
    const float* read_wrbf = (const float*)d_in[25];
    const float* read_w1   = (const float*)d_in[26];
    const float* read_b1   = (const float*)d_in[27];
    const float* read_w2   = (const float*)d_in[28];
    const float* read_b2   = (const float*)d_in[29];
    const float* read_w3   = (const float*)d_in[30];
    const float* read_b3   = (const float*)d_in[31];

    cudaFuncSetAttribute(chain_gemm, cudaFuncAttributeMaxDynamicSharedMemorySize,
                         CHAIN_SMEM);

    float *featA, *featB, *featC, *featD, *featE, *featF, *sw;
    float *at2, *results, *gsum, *gvar, *gcnt;
    int *eoff, *epos, *ecsr, *pinv, *esrcc, *paic, *aoff, *apos, *acsr;
    cudaGetSymbolAddress((void**)&featA, g_featA);
    cudaGetSymbolAddress((void**)&featB, g_featB);
    cudaGetSymbolAddress((void**)&featC, g_featC);
    cudaGetSymbolAddress((void**)&featD, g_featD);
    cudaGetSymbolAddress((void**)&featE, g_featE);
    cudaGetSymbolAddress((void**)&featF, g_featF);
    cudaGetSymbolAddress((void**)&sw, g_sw);
    cudaGetSymbolAddress((void**)&at2, g_at2);
    cudaGetSymbolAddress((void**)&results, g_results);
    cudaGetSymbolAddress((void**)&gsum, g_gsum);
    cudaGetSymbolAddress((void**)&gvar, g_gvar);
    cudaGetSymbolAddress((void**)&gcnt, g_gcnt);
    cudaGetSymbolAddress((void**)&eoff, g_eoff);
    cudaGetSymbolAddress((void**)&epos, g_epos);
    cudaGetSymbolAddress((void**)&ecsr, g_ecsr);
    cudaGetSymbolAddress((void**)&pinv, g_pinv);
    cudaGetSymbolAddress((void**)&esrcc, g_esrcc);
    cudaGetSymbolAddress((void**)&paic, g_paic);
    cudaGetSymbolAddress((void**)&aoff, g_aoff);
    cudaGetSymbolAddress((void**)&apos, g_apos);
    cudaGetSymbolAddress((void**)&acsr, g_acsr);

    cudaMemsetAsync(results, 0, AA * sizeof(float));
    cudaMemsetAsync(gcnt, 0, GG * sizeof(float));
    cudaMemsetAsync(d_out, 0, GG * sizeof(float));
    count_nodes<<<(NN + 255) / 256, 256>>>(nbatch, gcnt);

    // ---- build CSRs ----
    cudaMemsetAsync(eoff, 0, (NN + 1) * sizeof(int));
    hist_seg<<<(EE + 255) / 256, 256>>>(eidx + EE, EE, eoff);
    scan_offsets<<<1, 1024>>>(eoff, NN);
    cudaMemcpyAsync(epos, eoff, NN * sizeof(int), cudaMemcpyDeviceToDevice);
    fill_csr<<<(EE + 255) / 256, 256>>>(eidx + EE, EE, epos, ecsr, pinv);
    perm_edges<<<(EE + 255) / 256, 256>>>(ecsr, eidx, pai, esrcc, paic);

    cudaMemsetAsync(aoff, 0, (AA + 1) * sizeof(int));
    hist_seg<<<(NN + 255) / 256, 256>>>(idx0, NN, aoff);
    scan_offsets<<<1, 1024>>>(aoff, AA);
    cudaMemcpyAsync(apos, aoff, AA * sizeof(int), cudaMemcpyDeviceToDevice);
    fill_csr<<<(NN + 255) / 256, 256>>>(idx0, NN, apos, acsr, (int*)nullptr);

    auto one = [&](GDesc d) {
        GBatch gb; gb.d[0] = d;
        gemm_h3<<<dim3((d.M + 127) / 128, 1), 256>>>(gb, nbatch, gsum, gvar, gcnt);
    };

    const float* cur = x;

    for (int i = 0; i < LL; i++) {
        size_t dd = (size_t)i * DD * DD;
        float* kt = (cur == featC) ? featD : featC;

        // ---- 1) big batch: q, k, v, sbf (permuted), readout-gate(i) ----
        {
            GBatch gb;
            gb.d[0] = mkd(cur, conv_wq + dd, nullptr, nullptr, nullptr, featB, nullptr,
                          NN, DD, 0);
            gb.d[1] = mkd(cur, conv_wk + dd, nullptr, nullptr, nullptr, kt, nullptr,
                          NN, DD, 0);
            gb.d[2] = mkd(cur, conv_wv + dd, nullptr, nullptr, nullptr, featE, nullptr,
                          NN, DD, 0);
            gb.d[3] = mkd(edge_sbf, conv_wsbf + (size_t)i * SBFD * DD,
                          conv_bsbf + (size_t)i * DD, nullptr, nullptr, sw, pinv,
                          EE, SBFD, 0);
            gb.d[4] = mkd(node_rbf, read_wrbf + (size_t)i * RBFD * DD, nullptr, nullptr,
                          cur, featF, nullptr, NN, RBFD, EP_MUL);
            gemm_h3<<<dim3((EE + 127) / 128, 5), 256>>>(gb, nbatch, gsum, gvar, gcnt);
        }
        // ---- 2) chains: y0 = edge (gather cur -> w1 -> w2 -> we -> at2),
        //               y1 = readout(i) (gather featF -> w1 -> w2 -> dot) ----
        {
            CArgs2 ca;
            CArgs& ea = ca.a[0];
            ea.ns = 3;
            ea.st[0] = {edgenn_w1 + dd, edgenn_b1 + (size_t)i * DD, nullptr, CF_SILU, 0, 1};
            ea.st[1] = {edgenn_w2 + dd, edgenn_b2 + (size_t)i * DD, nullptr, 0, 1, 0};
            ea.st[2] = {conv_we + dd, nullptr, at2, 0, 0, 2};
            ea.gsrc = cur; ea.dotw = nullptr; ea.dotb = nullptr; ea.dotres = nullptr;
            CArgs& ra = ca.a[1];
            ra.ns = 2;
            ra.st[0] = {read_w1 + (size_t)i * DD * DD, read_b1 + (size_t)i * DD,
                        nullptr, CF_SILU, 0, 1};
            ra.st[1] = {read_w2 + (size_t)i * DD * DD, read_b2 + (size_t)i * DD,
                        nullptr, CF_SILU, 1, 0};
            ra.st[2] = {nullptr, nullptr, nullptr, 0, 0, 2};
            ra.gsrc = featF; ra.dotw = read_w3 + (size_t)i * DD;
            ra.dotb = read_b3 + i; ra.dotres = results;
            chain_gemm<<<dim3((AA + 127) / 128, 2), 256, CHAIN_SMEM>>>(ca, AA, aoff, acsr);
        }
        // ---- 3) attention -> featA ----
        attn_csr<<<(NN * 32 + 255) / 256, 256>>>(featB, kt, featE, at2, sw,
                                                 esrcc, paic, eoff, featA);
        // ---- 4) gate: msg * (node_rbf @ conv_wrbf) -> featB ----
        one(mkd(node_rbf, conv_wrbf + (size_t)i * RBFD * DD, nullptr, nullptr,
                featA, featB, nullptr, NN, RBFD, EP_MUL));
        // ---- 5) graph-norm stats (apply is fused into bf1/bf2) ----
        cudaMemsetAsync(gsum, 0, GG * sizeof(float));
        cudaMemsetAsync(gvar, 0, GG * sizeof(float));
        gn_sum<<<(NN * 32 + 255) / 256, 256>>>(featB, nbatch, gsum);
        gn_var<<<(NN * 32 + 255) / 256, 256>>>(featB, nbatch, gsum, gcnt, gvar);
        // ---- 6) residual chain ----
        one(mkd(featB, bf_w + (size_t)(i * 2 + 0) * DD * DD, bf_b + (size_t)(i * 2 + 0) * DD,
                nullptr, nullptr, kt, nullptr, NN, DD, EP_SILU | EP_GNA));
        one(mkd(kt, bf_w + (size_t)(i * 2 + 1) * DD * DD, bf_b + (size_t)(i * 2 + 1) * DD,
                featB, nullptr, featB, nullptr, NN, DD, EP_SILU | EP_RES | EP_GNRES));
        one(mkd(featB, dense_w + dd, dense_b + (size_t)i * DD, cur, nullptr, kt, nullptr,
                NN, DD, EP_SILU | EP_RES));
        one(mkd(kt, af_w + (size_t)(i * 4 + 0) * DD * DD, af_b + (size_t)(i * 4 + 0) * DD,
                nullptr, nullptr, featB, nullptr, NN, DD, EP_SILU));
        one(mkd(featB, af_w + (size_t)(i * 4 + 1) * DD * DD, af_b + (size_t)(i * 4 + 1) * DD,
                kt, nullptr, kt, nullptr, NN, DD, EP_SILU | EP_RES));
        one(mkd(kt, af_w + (size_t)(i * 4 + 2) * DD * DD, af_b + (size_t)(i * 4 + 2) * DD,
                nullptr, nullptr, featB, nullptr, NN, DD, EP_SILU));
        one(mkd(featB, af_w + (size_t)(i * 4 + 3) * DD * DD, af_b + (size_t)(i * 4 + 3) * DD,
                kt, nullptr, kt, nullptr, NN, DD, EP_SILU | EP_RES));
        cur = kt;
    }

    // ---- final readout(L) on last layer output ----
    one(mkd(node_rbf, read_wrbf + (size_t)LL * RBFD * DD, nullptr, nullptr, cur, featF,
            nullptr, NN, RBFD, EP_MUL));
    {
        CArgs2 ca;
        CArgs& ra = ca.a[0];
        ra.ns = 2;
        ra.st[0] = {read_w1 + (size_t)LL * DD * DD, read_b1 + (size_t)LL * DD,
                    nullptr, CF_SILU, 0, 1};
        ra.st[1] = {read_w2 + (size_t)LL * DD * DD, read_b2 + (size_t)LL * DD,
                    nullptr, CF_SILU, 1, 0};
        ra.st[2] = {nullptr, nullptr, nullptr, 0, 0, 2};
        ra.gsrc = featF; ra.dotw = read_w3 + (size_t)LL * DD;
        ra.dotb = read_b3 + LL; ra.dotres = results;
        ca.a[1] = ra;
        chain_gemm<<<dim3((AA + 127) / 128, 1), 256, CHAIN_SMEM>>>(ca, AA, aoff, acsr);
    }

    final_scatter<<<(AA + 255) / 256, 256>>>(results, abatch, (float*)d_out);
}